// round 3
// baseline (speedup 1.0000x reference)
#include <cuda_runtime.h>
#include <math.h>

#define BB   16384
#define EE   8
#define CC   1000
#define DD   59
#define HH1  256
#define HH2  128
#define FEPS 1e-8f
#define LNEPS 1e-5f
#define LN2F 0.69314718055994530942f

__device__ float g_W2T[HH1*HH2];   // W2 transposed: [j2][i] = W2[i][j2]

__device__ __forceinline__ float clipf(float v) {
    return fminf(fmaxf(v, -100.f), 100.f);
}

// ---------------------------------------------------------------------------
// Kernel 0: transpose W2 (256x128) -> g_W2T (128x256). One-time, tiny.
// ---------------------------------------------------------------------------
__global__ void w2t_kernel(const float* __restrict__ W2)
{
    int t = blockIdx.x * 256 + threadIdx.x;
    if (t < HH1*HH2) {
        int i = t >> 7;        // 0..255
        int j = t & 127;       // 0..127
        g_W2T[j*HH1 + i] = W2[t];
    }
}

// ---------------------------------------------------------------------------
// Kernel A: feature extraction, WARP-PER-ITEM (no block barriers).
// dyn smem: per-warp mean4[256] + L4[256] float4 = 8KB/warp, 8 warps = 64KB.
// ---------------------------------------------------------------------------
__global__ void __launch_bounds__(256) feat_kernel(const float* __restrict__ P,
                                                   float* __restrict__ feats,
                                                   int b_begin, int b_end)
{
    extern __shared__ float sml[];
    const int tid  = threadIdx.x;
    const int lane = tid & 31;
    const int wid  = tid >> 5;

    float4* smean4 = reinterpret_cast<float4*>(sml + wid*2048);  // 256 float4
    float4* sL4    = smean4 + 256;

    const int gw = blockIdx.x*8 + wid;
    const int nw = gridDim.x*8;

    for (int b = b_begin + gw; b < b_end; b += nw) {
        const float4* base = reinterpret_cast<const float4*>(P + (size_t)b*(EE*CC));
        float* fb = feats + (size_t)b * DD;

        // ---- pass 1: mean over experts, log2(mean+eps) ----
        float ge2 = 0.f, gent = 0.f;
        #pragma unroll
        for (int k = 0; k < 8; k++) {
            int t = lane + 32*k;
            if (t < 250) {
                float4 m = base[t];   // e = 0
                #pragma unroll
                for (int e = 1; e < EE; e++) {
                    float4 p = base[e*250 + t];
                    m.x += p.x; m.y += p.y; m.z += p.z; m.w += p.w;
                }
                m.x *= 0.125f; m.y *= 0.125f; m.z *= 0.125f; m.w *= 0.125f;
                float4 L;
                L.x = __log2f(m.x + FEPS);
                L.y = __log2f(m.y + FEPS);
                L.z = __log2f(m.z + FEPS);
                L.w = __log2f(m.w + FEPS);
                smean4[t] = m;
                sL4[t]    = L;
                ge2  += m.x*m.x + m.y*m.y + m.z*m.z + m.w*m.w;
                gent += m.x*L.x + m.y*L.y + m.z*L.z + m.w*L.w;
            }
        }
        #pragma unroll
        for (int off = 16; off; off >>= 1) {
            ge2  += __shfl_xor_sync(0xffffffffu, ge2,  off);
            gent += __shfl_xor_sync(0xffffffffu, gent, off);
        }
        const float mn = fmaxf(sqrtf(ge2), FEPS);

        // ---- pass 2: per-expert fused scan ----
        float totsq = 0.f;
        float mymax = 0.f;    // lane e holds max_probs[e]
        for (int e = 0; e < EE; e++) {
            float slp = 0.f, sq = 0.f, dtv = 0.f, pl = 0.f;
            float v0 = -1.f, v1 = -1.f, v2 = -1.f, v3 = -1.f, v4 = -1.f;
            #pragma unroll
            for (int k = 0; k < 8; k++) {
                int t = lane + 32*k;
                if (t < 250) {
                    float4 p  = base[e*250 + t];
                    float4 mm = smean4[t];
                    float4 LL = sL4[t];
                    #define DOELEM(px, mx, lx)                                   \
                    {                                                            \
                        float lp = __log2f((px) + FEPS);                         \
                        slp += (px)*lp;                                          \
                        sq  += (px)*(px);                                        \
                        dtv += (px)*(mx);                                        \
                        pl  += (px)*(lx);                                        \
                        if ((px) > v4) {                                         \
                            v4 = (px);                                           \
                            if (v4 > v3) { float tt=v3; v3=v4; v4=tt; }          \
                            if (v3 > v2) { float tt=v2; v2=v3; v3=tt; }          \
                            if (v2 > v1) { float tt=v1; v1=v2; v2=tt; }          \
                            if (v1 > v0) { float tt=v0; v0=v1; v1=tt; }          \
                        }                                                        \
                    }
                    DOELEM(p.x, mm.x, LL.x)
                    DOELEM(p.y, mm.y, LL.y)
                    DOELEM(p.z, mm.z, LL.z)
                    DOELEM(p.w, mm.w, LL.w)
                    #undef DOELEM
                }
            }
            #pragma unroll
            for (int off = 16; off; off >>= 1) {
                slp += __shfl_xor_sync(0xffffffffu, slp, off);
                sq  += __shfl_xor_sync(0xffffffffu, sq,  off);
                dtv += __shfl_xor_sync(0xffffffffu, dtv, off);
                pl  += __shfl_xor_sync(0xffffffffu, pl,  off);
            }
            float o0, o1, o2, o3, o4;
            #pragma unroll
            for (int r = 0; r < 5; r++) {
                float cur = v0;
                float mx = cur;
                #pragma unroll
                for (int off = 16; off; off >>= 1)
                    mx = fmaxf(mx, __shfl_xor_sync(0xffffffffu, mx, off));
                unsigned msk = __ballot_sync(0xffffffffu, cur == mx);
                int src = __ffs(msk) - 1;
                if (lane == src) { v0 = v1; v1 = v2; v2 = v3; v3 = v4; v4 = -1.f; }
                if (r == 0) o0 = mx; else if (r == 1) o1 = mx;
                else if (r == 2) o2 = mx; else if (r == 3) o3 = mx; else o4 = mx;
            }
            totsq += sq;
            if (lane == e) mymax = o0;
            if (lane == 0) {
                float ent  = -slp * LN2F;
                float mass = o0 + o1 + o2 + o3 + o4;
                float pn   = fmaxf(sqrtf(sq), FEPS);
                fb[0*EE + e] = clipf(ent);
                fb[1*EE + e] = clipf(mass);
                fb[2*EE + e] = clipf(1.f - mass);
                fb[3*EE + e] = clipf(o0);
                fb[4*EE + e] = clipf(o0 - o1);
                fb[5*EE + e] = clipf(dtv / (pn * mn));
                fb[6*EE + e] = clipf((slp - pl) * LN2F);
            }
        }

        // ---- global features ----
        float xv = (lane < 8) ? mymax : 0.f;
        float s = xv;
        #pragma unroll
        for (int off = 16; off; off >>= 1) s += __shfl_xor_sync(0xffffffffu, s, off);
        float mu = s * 0.125f;
        float d  = (lane < 8) ? (mymax - mu) : 0.f;
        float dv = d * d;
        #pragma unroll
        for (int off = 16; off; off >>= 1) dv += __shfl_xor_sync(0xffffffffu, dv, off);
        if (lane == 0) {
            fb[56] = clipf(-gent * LN2F);
            fb[57] = clipf((totsq - 8.f * ge2) * (1.f / 7000.f));
            fb[58] = clipf(sqrtf(dv * (1.f / 7.f)));
        }
    }
}

// ---------------------------------------------------------------------------
// Kernel B: MLP, 512 threads, 16 rows per iteration.
// W1 transposed+swizzled in smem (float4, conflict-free), W2T via LDG.128.
// ---------------------------------------------------------------------------
__global__ void __launch_bounds__(512, 2) mlp_kernel(
    const float* __restrict__ feats,
    const float* __restrict__ W1, const float* __restrict__ b1,
    const float* __restrict__ g1, const float* __restrict__ be1,
    const float* __restrict__ b2, const float* __restrict__ g2,
    const float* __restrict__ be2,
    const float* __restrict__ W3, const float* __restrict__ b3,
    float* __restrict__ wout, float* __restrict__ lout)
{
    extern __shared__ float sm[];
    float* sW1T = sm;                  // 256*64 = 16384 (swizzled float4 chunks)
    float* sW3T = sW1T + 256*64;       // 8*132  = 1056
    float* sb1  = sW3T + 8*132;        // 256
    float* sg1  = sb1  + HH1;          // 256
    float* sbe1 = sg1  + HH1;          // 256
    float* sb2  = sbe1 + HH1;          // 128
    float* sg2  = sb2  + HH2;          // 128
    float* sbe2 = sg2  + HH2;          // 128
    float* sb3  = sbe2 + HH2;          // 8
    float* sf   = sb3  + EE;           // 16*60 = 960
    float* sh1  = sf   + 16*60;        // 16*256 = 4096
    float* sh2  = sh1  + 16*HH1;       // 16*128 = 2048
    float* sred = sh2  + 16*HH2;       // 256 (sums 0..127, squares 128..255)
    float* smu  = sred + 256;          // 16
    float* srs  = smu  + 16;           // 16

    const int tid  = threadIdx.x;
    const int lane = tid & 31;
    const int wid  = tid >> 5;         // 0..15
    const int j1   = tid & 255;        // layer1 output column
    const int h    = tid >> 8;         // 0..1 -> rows h*8..h*8+7
    const int j2   = tid & 127;        // layer2 output column
    const int rg   = tid >> 7;         // 0..3 -> rows rg*4..rg*4+3

    // ---- stage weights (zero first, then fill: sync between) ----
    for (int t = tid; t < 256*64; t += 512) sW1T[t] = 0.f;
    for (int t = tid; t < 8*132;  t += 512) sW3T[t] = 0.f;
    __syncthreads();
    for (int t = tid; t < DD*HH1; t += 512) {
        int i = t >> 8;          // 0..58
        int j = t & 255;
        int c = i >> 2;
        sW1T[j*64 + ((c ^ (j & 15)) << 2) + (i & 3)] = W1[t];
    }
    for (int t = tid; t < HH2*EE; t += 512) {
        int i = t >> 3;          // 0..127
        int o = t & 7;
        sW3T[o*132 + i] = W3[t];
    }
    for (int t = tid; t < HH1; t += 512) { sb1[t] = b1[t]; sg1[t] = g1[t]; sbe1[t] = be1[t]; }
    for (int t = tid; t < HH2; t += 512) { sb2[t] = b2[t]; sg2[t] = g2[t]; sbe2[t] = be2[t]; }
    if (tid < EE) sb3[tid] = b3[tid];
    __syncthreads();

    const int nchunks = BB / 16;   // 1024
    for (int chunk = blockIdx.x; chunk < nchunks; chunk += gridDim.x) {
        const int row0 = chunk * 16;

        for (int t = tid; t < 16*DD; t += 512) {
            int r = t / DD, i = t - r*DD;
            sf[r*60 + i] = feats[(size_t)row0 * DD + t];
        }
        if (tid < 16) sf[tid*60 + 59] = 0.f;
        __syncthreads();

        // ---- layer 1: 59 -> 256, 8 rows per thread ----
        float acc[8];
        #pragma unroll
        for (int r = 0; r < 8; r++) acc[r] = sb1[j1];
        #pragma unroll
        for (int c = 0; c < 15; c++) {
            const float4 w = *reinterpret_cast<const float4*>(
                &sW1T[j1*64 + ((c ^ (j1 & 15)) << 2)]);
            #pragma unroll
            for (int r = 0; r < 8; r++) {
                const float4 a = *reinterpret_cast<const float4*>(
                    &sf[(h*8 + r)*60 + (c << 2)]);
                acc[r] += a.x*w.x + a.y*w.y + a.z*w.z + a.w*w.w;
            }
        }
        // LN over 256 columns, per row
        {
            float sv[8], sq[8];
            #pragma unroll
            for (int r = 0; r < 8; r++) { sv[r] = acc[r]; sq[r] = acc[r]*acc[r]; }
            #pragma unroll
            for (int off = 16; off; off >>= 1) {
                #pragma unroll
                for (int r = 0; r < 8; r++) {
                    sv[r] += __shfl_xor_sync(0xffffffffu, sv[r], off);
                    sq[r] += __shfl_xor_sync(0xffffffffu, sq[r], off);
                }
            }
            if (lane == 0) {
                #pragma unroll
                for (int r = 0; r < 8; r++) {
                    sred[wid*8 + r]       = sv[r];
                    sred[128 + wid*8 + r] = sq[r];
                }
            }
        }
        __syncthreads();
        if (tid < 16) {
            int row = tid, hh = row >> 3, rl = row & 7;
            float a = 0.f, q = 0.f;
            #pragma unroll
            for (int w = 0; w < 8; w++) {
                a += sred[(hh*8 + w)*8 + rl];
                q += sred[128 + (hh*8 + w)*8 + rl];
            }
            float muv = a * (1.f/256.f);
            float var = q * (1.f/256.f) - muv*muv;
            smu[row] = muv;
            srs[row] = rsqrtf(var + LNEPS);
        }
        __syncthreads();
        #pragma unroll
        for (int r = 0; r < 8; r++) {
            int row = h*8 + r;
            float hv = (acc[r] - smu[row]) * srs[row] * sg1[j1] + sbe1[j1];
            sh1[row*HH1 + j1] = fmaxf(hv, 0.f);
        }
        __syncthreads();

        // ---- layer 2: 256 -> 128, W2T from L2 via LDG.128, 4 rows/thread ----
        float acc2[4];
        #pragma unroll
        for (int r = 0; r < 4; r++) acc2[r] = sb2[j2];
        {
            const float4* w2 = reinterpret_cast<const float4*>(g_W2T) + j2*64;
            #pragma unroll 8
            for (int c = 0; c < 64; c++) {
                float4 w = __ldg(&w2[c]);
                #pragma unroll
                for (int r = 0; r < 4; r++) {
                    const float4 a = *reinterpret_cast<const float4*>(
                        &sh1[(rg*4 + r)*HH1 + (c << 2)]);
                    acc2[r] += a.x*w.x + a.y*w.y + a.z*w.z + a.w*w.w;
                }
            }
        }
        // LN over 128 columns
        {
            float sv[4], sq[4];
            #pragma unroll
            for (int r = 0; r < 4; r++) { sv[r] = acc2[r]; sq[r] = acc2[r]*acc2[r]; }
            #pragma unroll
            for (int off = 16; off; off >>= 1) {
                #pragma unroll
                for (int r = 0; r < 4; r++) {
                    sv[r] += __shfl_xor_sync(0xffffffffu, sv[r], off);
                    sq[r] += __shfl_xor_sync(0xffffffffu, sq[r], off);
                }
            }
            if (lane == 0) {
                #pragma unroll
                for (int r = 0; r < 4; r++) {
                    sred[wid*4 + r]       = sv[r];
                    sred[128 + wid*4 + r] = sq[r];
                }
            }
        }
        __syncthreads();
        if (tid < 16) {
            int row = tid, gg = row >> 2, rl = row & 3;
            float a = 0.f, q = 0.f;
            #pragma unroll
            for (int w = 0; w < 4; w++) {
                a += sred[(gg*4 + w)*4 + rl];
                q += sred[128 + (gg*4 + w)*4 + rl];
            }
            float muv = a * (1.f/128.f);
            float var = q * (1.f/128.f) - muv*muv;
            smu[row] = muv;
            srs[row] = rsqrtf(var + LNEPS);
        }
        __syncthreads();
        #pragma unroll
        for (int r = 0; r < 4; r++) {
            int row = rg*4 + r;
            float hv = (acc2[r] - smu[row]) * srs[row] * sg2[j2] + sbe2[j2];
            sh2[row*HH2 + j2] = fmaxf(hv, 0.f);
        }
        __syncthreads();

        // ---- layer 3 + softmax (128 threads: 16 rows x 8 outputs) ----
        if (tid < 128) {
            int r = tid >> 3, o = tid & 7;
            float a = sb3[o];
            #pragma unroll
            for (int c = 0; c < 32; c++) {
                const float4 hv = *reinterpret_cast<const float4*>(&sh2[r*HH2 + (c << 2)]);
                const float4 w  = *reinterpret_cast<const float4*>(&sW3T[o*132 + (c << 2)]);
                a += hv.x*w.x + hv.y*w.y + hv.z*w.z + hv.w*w.w;
            }
            float mx = a;
            #pragma unroll
            for (int off = 4; off; off >>= 1)
                mx = fmaxf(mx, __shfl_xor_sync(0xffffffffu, mx, off));
            float ex = __expf(a - mx);
            float sme = ex;
            #pragma unroll
            for (int off = 4; off; off >>= 1)
                sme += __shfl_xor_sync(0xffffffffu, sme, off);
            const int row = row0 + r;
            lout[(size_t)row*EE + o] = a;
            wout[(size_t)row*EE + o] = ex / sme;
        }
        __syncthreads();
    }
}

// ---------------------------------------------------------------------------
extern "C" void kernel_launch(void* const* d_in, const int* in_sizes, int n_in,
                              void* d_out, int out_size)
{
    (void)in_sizes; (void)n_in; (void)out_size;
    const float* P   = (const float*)d_in[0];
    const float* W1  = (const float*)d_in[1];
    const float* b1  = (const float*)d_in[2];
    const float* g1  = (const float*)d_in[3];
    const float* be1 = (const float*)d_in[4];
    const float* W2  = (const float*)d_in[5];
    const float* b2  = (const float*)d_in[6];
    const float* g2  = (const float*)d_in[7];
    const float* be2 = (const float*)d_in[8];
    const float* W3  = (const float*)d_in[9];
    const float* b3  = (const float*)d_in[10];

    float* out   = (float*)d_out;
    float* wout  = out;                    // weights: B*8
    float* lout  = out + (size_t)BB*EE;    // logits:  B*8
    float* feats = out + (size_t)2*BB*EE;  // feats:   B*59

    w2t_kernel<<<128, 256>>>(W2);

    const size_t smemA = (size_t)(8 * 2048) * sizeof(float);   // 64 KB
    cudaFuncSetAttribute(feat_kernel, cudaFuncAttributeMaxDynamicSharedMemorySize, (int)smemA);
    feat_kernel<<<296, 256, smemA>>>(P, feats, 0, BB/2);
    feat_kernel<<<296, 256, smemA>>>(P, feats, BB/2, BB);

    const size_t smemB = (size_t)(256*64 + 8*132 + 3*HH1 + 3*HH2 + EE
                                  + 16*60 + 16*HH1 + 16*HH2 + 256 + 32) * sizeof(float);
    cudaFuncSetAttribute(mlp_kernel, cudaFuncAttributeMaxDynamicSharedMemorySize, (int)smemB);
    mlp_kernel<<<296, 512, smemB>>>(feats, W1, b1, g1, be1, b2, g2, be2, W3, b3,
                                    wout, lout);
}

// round 4
// speedup vs baseline: 1.4186x; 1.4186x over previous
#include <cuda_runtime.h>
#include <math.h>

#define BB   16384
#define EE   8
#define CC   1000
#define DD   59
#define HH1  256
#define HH2  128
#define FEPS 1e-8f
#define LNEPS 1e-5f
#define LN2F 0.69314718055994530942f

// ---------------------------------------------------------------------------
__device__ __forceinline__ void cp_async16(void* smem_ptr, const void* gmem) {
    unsigned s = (unsigned)__cvta_generic_to_shared(smem_ptr);
    asm volatile("cp.async.cg.shared.global [%0], [%1], 16;\n" :: "r"(s), "l"(gmem));
}
#define CP_COMMIT() asm volatile("cp.async.commit_group;\n" ::: "memory")
#define CP_WAIT1()  asm volatile("cp.async.wait_group 1;\n" ::: "memory")

// ---------------------------------------------------------------------------
// Kernel A: feature extraction. 256 thr/block, cp.async double-buffered.
// dynamic smem: buf[2][8000] + smean[1000] + sL[1000]  = 72000 B
// Top-5 via branch-free FMNMX insertion network (no predicated dep chains).
// ---------------------------------------------------------------------------
__global__ void __launch_bounds__(256) feat_kernel(const float* __restrict__ P,
                                                   float* __restrict__ feats)
{
    extern __shared__ float dyn[];
    float* buf0  = dyn;               // 8000
    float* buf1  = dyn + 8000;        // 8000
    float* smean = dyn + 16000;       // 1000
    float* sL    = dyn + 17000;       // 1000

    __shared__ float s_feat[64];
    __shared__ float s_sq[EE];
    __shared__ float s_red[16];
    __shared__ float s_ge2, s_gent;

    const int tid  = threadIdx.x;
    const int lane = tid & 31;
    const int wid  = tid >> 5;

    float* bufs[2] = {buf0, buf1};

    // prime the pipeline
    int b0 = blockIdx.x;
    if (b0 < BB) {
        const float4* src = reinterpret_cast<const float4*>(P + (size_t)b0*(EE*CC));
        float4* dst = reinterpret_cast<float4*>(buf0);
        for (int i = tid; i < EE*CC/4; i += 256) cp_async16(&dst[i], &src[i]);
    }
    CP_COMMIT();

    int cur = 0;
    for (int b = b0; b < BB; b += gridDim.x) {
        int nb = b + gridDim.x;
        if (nb < BB) {
            const float4* src = reinterpret_cast<const float4*>(P + (size_t)nb*(EE*CC));
            float4* dst = reinterpret_cast<float4*>(bufs[cur^1]);
            for (int i = tid; i < EE*CC/4; i += 256) cp_async16(&dst[i], &src[i]);
        }
        CP_COMMIT();
        CP_WAIT1();            // current buffer ready
        __syncthreads();

        const float* sp = bufs[cur];

        // ---- phase 1: mean over experts (float4), log2(mean+eps), global sums ----
        float ge2 = 0.f, gent = 0.f;
        if (tid < CC/4) {
            const float4* pb = reinterpret_cast<const float4*>(sp);
            float4 m = make_float4(0.f, 0.f, 0.f, 0.f);
            #pragma unroll
            for (int e = 0; e < EE; e++) {
                float4 p = pb[e*(CC/4) + tid];
                m.x += p.x; m.y += p.y; m.z += p.z; m.w += p.w;
            }
            m.x *= 0.125f; m.y *= 0.125f; m.z *= 0.125f; m.w *= 0.125f;
            float4 L;
            L.x = __log2f(m.x + FEPS);
            L.y = __log2f(m.y + FEPS);
            L.z = __log2f(m.z + FEPS);
            L.w = __log2f(m.w + FEPS);
            reinterpret_cast<float4*>(smean)[tid] = m;
            reinterpret_cast<float4*>(sL)[tid]    = L;
            ge2  = m.x*m.x + m.y*m.y + m.z*m.z + m.w*m.w;
            gent = m.x*L.x + m.y*L.y + m.z*L.z + m.w*L.w;
        }
        #pragma unroll
        for (int off = 16; off; off >>= 1) {
            ge2  += __shfl_xor_sync(0xffffffffu, ge2,  off);
            gent += __shfl_xor_sync(0xffffffffu, gent, off);
        }
        if (lane == 0) { s_red[wid] = ge2; s_red[8 + wid] = gent; }
        __syncthreads();
        if (tid == 0) {
            float a = 0.f, g = 0.f;
            #pragma unroll
            for (int w = 0; w < 8; w++) { a += s_red[w]; g += s_red[8 + w]; }
            s_ge2 = a; s_gent = g;
        }
        __syncthreads();

        // ---- phase 2: one warp per expert, fused scan ----
        {
            const float mn = fmaxf(sqrtf(s_ge2), FEPS);
            const float4* row = reinterpret_cast<const float4*>(sp + wid*CC);
            const float4* m4  = reinterpret_cast<const float4*>(smean);
            const float4* L4  = reinterpret_cast<const float4*>(sL);

            float slp = 0.f, sq = 0.f, dtv = 0.f, pl = 0.f;
            float v0 = -1.f, v1 = -1.f, v2 = -1.f, v3 = -1.f, v4 = -1.f;

            #pragma unroll
            for (int k = 0; k < 8; k++) {
                int t = lane + 32*k;
                if (t < 250) {
                    float4 p  = row[t];
                    float4 mm = m4[t];
                    float4 LL = L4[t];
                    // Branch-free sorted-insert: min/max cascade, no predicates.
                    #define DOELEM(px, mx, lx)                                   \
                    {                                                            \
                        float lp = __log2f((px) + FEPS);                         \
                        slp += (px)*lp;                                          \
                        sq  += (px)*(px);                                        \
                        dtv += (px)*(mx);                                        \
                        pl  += (px)*(lx);                                        \
                        float t0 = fminf(v0, (px)); v0 = fmaxf(v0, (px));        \
                        float t1 = fminf(v1, t0);   v1 = fmaxf(v1, t0);          \
                        float t2 = fminf(v2, t1);   v2 = fmaxf(v2, t1);          \
                        float t3 = fminf(v3, t2);   v3 = fmaxf(v3, t2);          \
                        v4 = fmaxf(v4, t3);                                      \
                    }
                    DOELEM(p.x, mm.x, LL.x)
                    DOELEM(p.y, mm.y, LL.y)
                    DOELEM(p.z, mm.z, LL.z)
                    DOELEM(p.w, mm.w, LL.w)
                    #undef DOELEM
                }
            }
            #pragma unroll
            for (int off = 16; off; off >>= 1) {
                slp += __shfl_xor_sync(0xffffffffu, slp, off);
                sq  += __shfl_xor_sync(0xffffffffu, sq,  off);
                dtv += __shfl_xor_sync(0xffffffffu, dtv, off);
                pl  += __shfl_xor_sync(0xffffffffu, pl,  off);
            }
            float o0, o1, o2, o3, o4;
            #pragma unroll
            for (int r = 0; r < 5; r++) {
                float cur_v = v0;
                float mx = cur_v;
                #pragma unroll
                for (int off = 16; off; off >>= 1)
                    mx = fmaxf(mx, __shfl_xor_sync(0xffffffffu, mx, off));
                unsigned msk = __ballot_sync(0xffffffffu, cur_v == mx);
                int src = __ffs(msk) - 1;
                if (lane == src) { v0 = v1; v1 = v2; v2 = v3; v3 = v4; v4 = -1.f; }
                if (r == 0) o0 = mx; else if (r == 1) o1 = mx;
                else if (r == 2) o2 = mx; else if (r == 3) o3 = mx; else o4 = mx;
            }

            if (lane == 0) {
                float ent  = -slp * LN2F;
                float mass = o0 + o1 + o2 + o3 + o4;
                float pn   = fmaxf(sqrtf(sq), FEPS);
                s_feat[0*EE + wid] = ent;
                s_feat[1*EE + wid] = mass;
                s_feat[2*EE + wid] = 1.f - mass;
                s_feat[3*EE + wid] = o0;
                s_feat[4*EE + wid] = o0 - o1;
                s_feat[5*EE + wid] = dtv / (pn * mn);
                s_feat[6*EE + wid] = (slp - pl) * LN2F;
                s_sq[wid] = sq;
            }
        }
        __syncthreads();

        if (tid == 0) {
            float totsq = 0.f;
            #pragma unroll
            for (int e = 0; e < EE; e++) totsq += s_sq[e];
            float mcv = (totsq - 8.f * s_ge2) * (1.f / 7000.f);
            float mu = 0.f;
            #pragma unroll
            for (int e = 0; e < EE; e++) mu += s_feat[3*EE + e];
            mu *= 0.125f;
            float var = 0.f;
            #pragma unroll
            for (int e = 0; e < EE; e++) {
                float d = s_feat[3*EE + e] - mu;
                var += d * d;
            }
            s_feat[56] = -s_gent * LN2F;
            s_feat[57] = mcv;
            s_feat[58] = sqrtf(var * (1.f/7.f));
        }
        __syncthreads();

        if (tid < DD) {
            float v = s_feat[tid];
            v = fminf(fmaxf(v, -100.f), 100.f);
            feats[(size_t)b * DD + tid] = v;
        }
        __syncthreads();   // all reads of bufs[cur] done before it is refilled
        cur ^= 1;
    }
}

// ---------------------------------------------------------------------------
// Kernel B: MLP. 512 threads, 2 groups x 4 rows = 8 rows per iteration.
// W1/W3/biases in smem (~92KB -> 2 blocks/SM, 32 warps). W2 read from L2.
// (Exact revert to the R2 version measured at 119us.)
// ---------------------------------------------------------------------------
#define MROWS  4
#define GROUPS 2

__global__ void __launch_bounds__(512) mlp_kernel(
    const float* __restrict__ feats,
    const float* __restrict__ W1, const float* __restrict__ b1,
    const float* __restrict__ g1, const float* __restrict__ be1,
    const float* __restrict__ W2, const float* __restrict__ b2,
    const float* __restrict__ g2, const float* __restrict__ be2,
    const float* __restrict__ W3, const float* __restrict__ b3,
    float* __restrict__ wout, float* __restrict__ lout)
{
    extern __shared__ float sm[];
    float* sW1  = sm;                        // 59*256 = 15104
    float* sW3  = sW1  + DD*HH1;             // 128*8  = 1024
    float* sb1  = sW3  + HH2*EE;             // 256
    float* sg1  = sb1  + HH1;
    float* sbe1 = sg1  + HH1;
    float* sb2  = sbe1 + HH1;                // 128
    float* sg2  = sb2  + HH2;
    float* sbe2 = sg2  + HH2;
    float* sb3  = sbe2 + HH2;                // 8
    float* sf   = sb3  + EE;                 // 8*59   = 472
    float* sh1  = sf   + GROUPS*MROWS*DD;    // 8*256  = 2048
    float* sh2  = sh1  + GROUPS*MROWS*HH1;   // 8*128  = 1024
    float* spart= sh2  + GROUPS*MROWS*HH2;   // 2*1024 = 2048
    float* slog = spart+ GROUPS*2*HH2*MROWS; // 64
    float* sred = slog + GROUPS*MROWS*EE;    // 128 (sums at 0, squares at 64)
    float* smu  = sred + 128;                // 8
    float* srs  = smu  + GROUPS*MROWS;       // 8

    const int tid  = threadIdx.x;
    const int lane = tid & 31;
    const int wid  = tid >> 5;               // 0..15
    const int g    = tid >> 8;               // 0..1
    const int gtid = tid & 255;

    for (int i = tid; i < DD*HH1;  i += 512) sW1[i] = W1[i];
    for (int i = tid; i < HH2*EE;  i += 512) sW3[i] = W3[i];
    for (int i = tid; i < HH1;     i += 512) { sb1[i] = b1[i]; sg1[i] = g1[i]; sbe1[i] = be1[i]; }
    for (int i = tid; i < HH2;     i += 512) { sb2[i] = b2[i]; sg2[i] = g2[i]; sbe2[i] = be2[i]; }
    if (tid < EE) sb3[tid] = b3[tid];
    __syncthreads();

    const int RPC = GROUPS * MROWS;          // 8 rows per chunk
    const int nchunks = BB / RPC;            // 2048
    for (int chunk = blockIdx.x; chunk < nchunks; chunk += gridDim.x) {
        const int row0 = chunk * RPC;

        for (int i = tid; i < RPC*DD; i += 512)
            sf[i] = feats[(size_t)row0 * DD + i];
        __syncthreads();

        // ---- layer 1: 59 -> 256 ----
        float acc[MROWS];
        {
            const int j = gtid;
            #pragma unroll
            for (int r = 0; r < MROWS; r++) acc[r] = sb1[j];
            for (int i = 0; i < DD; i++) {
                float w = sW1[i*HH1 + j];
                #pragma unroll
                for (int r = 0; r < MROWS; r++) acc[r] += sf[(g*MROWS + r)*DD + i] * w;
            }
        }
        {
            float sv[MROWS], sq2[MROWS];
            #pragma unroll
            for (int r = 0; r < MROWS; r++) { sv[r] = acc[r]; sq2[r] = acc[r]*acc[r]; }
            #pragma unroll
            for (int off = 16; off; off >>= 1) {
                #pragma unroll
                for (int r = 0; r < MROWS; r++) {
                    sv[r]  += __shfl_xor_sync(0xffffffffu, sv[r],  off);
                    sq2[r] += __shfl_xor_sync(0xffffffffu, sq2[r], off);
                }
            }
            if (lane == 0) {
                #pragma unroll
                for (int r = 0; r < MROWS; r++) {
                    sred[wid*4 + r]      = sv[r];
                    sred[64 + wid*4 + r] = sq2[r];
                }
            }
        }
        __syncthreads();
        if (tid < RPC) {
            const int gg = tid >> 2;
            float a = 0.f, q = 0.f;
            #pragma unroll
            for (int w = 0; w < 8; w++) {
                a += sred[(gg*8 + w)*4 + (tid & 3)];
                q += sred[64 + (gg*8 + w)*4 + (tid & 3)];
            }
            float mu  = a * (1.f/256.f);
            float var = q * (1.f/256.f) - mu*mu;
            smu[tid] = mu;
            srs[tid] = rsqrtf(var + LNEPS);
        }
        __syncthreads();
        {
            const int j = gtid;
            #pragma unroll
            for (int r = 0; r < MROWS; r++) {
                float h = (acc[r] - smu[g*MROWS + r]) * srs[g*MROWS + r] * sg1[j] + sbe1[j];
                sh1[(g*MROWS + r)*HH1 + j] = fmaxf(h, 0.f);
            }
        }
        __syncthreads();

        // ---- layer 2: 256 -> 128, W2 from global (L2-resident), split-K=2 ----
        {
            const int j    = gtid & (HH2 - 1);
            const int half = gtid >> 7;
            float a2[MROWS];
            #pragma unroll
            for (int r = 0; r < MROWS; r++) a2[r] = 0.f;
            const int i0 = half * 128;
            #pragma unroll 4
            for (int i = i0; i < i0 + 128; i++) {
                float w = __ldg(&W2[i*HH2 + j]);
                #pragma unroll
                for (int r = 0; r < MROWS; r++) a2[r] += sh1[(g*MROWS + r)*HH1 + i] * w;
            }
            #pragma unroll
            for (int r = 0; r < MROWS; r++)
                spart[g*(2*HH2*MROWS) + (half*HH2 + j)*MROWS + r] = a2[r];
        }
        __syncthreads();
        float acc3[MROWS];
        if (gtid < HH2) {
            const int j = gtid;
            #pragma unroll
            for (int r = 0; r < MROWS; r++)
                acc3[r] = spart[g*(2*HH2*MROWS) + j*MROWS + r]
                        + spart[g*(2*HH2*MROWS) + (HH2 + j)*MROWS + r] + sb2[j];
            float sv[MROWS], sq2[MROWS];
            #pragma unroll
            for (int r = 0; r < MROWS; r++) { sv[r] = acc3[r]; sq2[r] = acc3[r]*acc3[r]; }
            #pragma unroll
            for (int off = 16; off; off >>= 1) {
                #pragma unroll
                for (int r = 0; r < MROWS; r++) {
                    sv[r]  += __shfl_xor_sync(0xffffffffu, sv[r],  off);
                    sq2[r] += __shfl_xor_sync(0xffffffffu, sq2[r], off);
                }
            }
            if (lane == 0) {
                #pragma unroll
                for (int r = 0; r < MROWS; r++) {
                    sred[wid*4 + r]      = sv[r];
                    sred[64 + wid*4 + r] = sq2[r];
                }
            }
        }
        __syncthreads();
        if (tid < RPC) {
            const int gg = tid >> 2;
            float a = 0.f, q = 0.f;
            #pragma unroll
            for (int w = 0; w < 4; w++) {
                a += sred[(gg*8 + w)*4 + (tid & 3)];
                q += sred[64 + (gg*8 + w)*4 + (tid & 3)];
            }
            float mu  = a * (1.f/128.f);
            float var = q * (1.f/128.f) - mu*mu;
            smu[tid] = mu;
            srs[tid] = rsqrtf(var + LNEPS);
        }
        __syncthreads();
        if (gtid < HH2) {
            #pragma unroll
            for (int r = 0; r < MROWS; r++) {
                float h = (acc3[r] - smu[g*MROWS + r]) * srs[g*MROWS + r] * sg2[gtid] + sbe2[gtid];
                sh2[(g*MROWS + r)*HH2 + gtid] = fmaxf(h, 0.f);
            }
        }
        __syncthreads();

        // ---- layer 3 + softmax ----
        if (tid < RPC*EE) {
            const int r = tid >> 3;      // 0..7 (global row within chunk)
            const int o = tid & 7;
            float a = sb3[o];
            #pragma unroll 8
            for (int i = 0; i < HH2; i++) a += sh2[r*HH2 + i] * sW3[i*EE + o];
            slog[r*EE + o] = a;

            float mx = a;
            #pragma unroll
            for (int off = 4; off; off >>= 1)
                mx = fmaxf(mx, __shfl_xor_sync(0xffffffffu, mx, off));
            float ex = __expf(a - mx);
            float sme = ex;
            #pragma unroll
            for (int off = 4; off; off >>= 1)
                sme += __shfl_xor_sync(0xffffffffu, sme, off);
            const int row = row0 + r;
            lout[(size_t)row*EE + o] = a;
            wout[(size_t)row*EE + o] = ex / sme;
        }
        __syncthreads();
    }
}

// ---------------------------------------------------------------------------
extern "C" void kernel_launch(void* const* d_in, const int* in_sizes, int n_in,
                              void* d_out, int out_size)
{
    (void)in_sizes; (void)n_in; (void)out_size;
    const float* P   = (const float*)d_in[0];
    const float* W1  = (const float*)d_in[1];
    const float* b1  = (const float*)d_in[2];
    const float* g1  = (const float*)d_in[3];
    const float* be1 = (const float*)d_in[4];
    const float* W2  = (const float*)d_in[5];
    const float* b2  = (const float*)d_in[6];
    const float* g2  = (const float*)d_in[7];
    const float* be2 = (const float*)d_in[8];
    const float* W3  = (const float*)d_in[9];
    const float* b3  = (const float*)d_in[10];

    float* out   = (float*)d_out;
    float* wout  = out;                    // weights: B*8
    float* lout  = out + (size_t)BB*EE;    // logits:  B*8
    float* feats = out + (size_t)2*BB*EE;  // feats:   B*59

    const size_t smemA = (size_t)(2*EE*CC + 2*CC) * sizeof(float);  // 72000 B
    cudaFuncSetAttribute(feat_kernel, cudaFuncAttributeMaxDynamicSharedMemorySize, (int)smemA);
    feat_kernel<<<444, 256, smemA>>>(P, feats);

    const size_t smemB = (size_t)(DD*HH1 + HH2*EE
                                  + 3*HH1 + 3*HH2 + EE
                                  + GROUPS*MROWS*DD + GROUPS*MROWS*HH1 + GROUPS*MROWS*HH2
                                  + GROUPS*2*HH2*MROWS + GROUPS*MROWS*EE + 128 + 16)
                         * sizeof(float);
    cudaFuncSetAttribute(mlp_kernel, cudaFuncAttributeMaxDynamicSharedMemorySize, (int)smemB);
    mlp_kernel<<<296, 512, smemB>>>(feats, W1, b1, g1, be1, W2, b2, g2, be2, W3, b3,
                                    wout, lout);
}

// round 6
// speedup vs baseline: 1.5877x; 1.1192x over previous
#include <cuda_runtime.h>
#include <math.h>

#define BB   16384
#define EE   8
#define CC   1000
#define DD   59
#define HH1  256
#define HH2  128
#define FEPS 1e-8f
#define LNEPS 1e-5f
#define LN2F 0.69314718055994530942f

// ---------------------------------------------------------------------------
__device__ __forceinline__ void cp_async16(void* smem_ptr, const void* gmem) {
    unsigned s = (unsigned)__cvta_generic_to_shared(smem_ptr);
    asm volatile("cp.async.cg.shared.global [%0], [%1], 16;\n" :: "r"(s), "l"(gmem));
}
#define CP_COMMIT() asm volatile("cp.async.commit_group;\n" ::: "memory")
#define CP_WAIT0()  asm volatile("cp.async.wait_group 0;\n" ::: "memory")

// ---------------------------------------------------------------------------
// Kernel A: feature extraction. 256 thr/block, single buffer, 4 blocks/SM.
// dyn smem: buf[8000] + sdtv[8*256] + spl[8*256] = 48384 B
// ---------------------------------------------------------------------------
__global__ void __launch_bounds__(256, 4) feat_kernel(const float* __restrict__ P,
                                                      float* __restrict__ feats)
{
    extern __shared__ float dyn[];
    float* buf  = dyn;             // 8000
    float* sdtv = dyn + 8000;      // 8*256
    float* spl  = sdtv + 8*256;    // 8*256

    __shared__ float s_feat[64];
    __shared__ float s_sq[EE];
    __shared__ float s_red[16];
    __shared__ float s_ge2, s_gent;

    const int tid  = threadIdx.x;
    const int lane = tid & 31;
    const int wid  = tid >> 5;

    for (int b = blockIdx.x; b < BB; b += gridDim.x) {
        // ---- stage item into smem ----
        {
            const float4* src = reinterpret_cast<const float4*>(P + (size_t)b*(EE*CC));
            float4* dst = reinterpret_cast<float4*>(buf);
            for (int i = tid; i < EE*CC/4; i += 256) cp_async16(&dst[i], &src[i]);
        }
        CP_COMMIT();
        CP_WAIT0();
        __syncthreads();

        // ---- phase 1: mean, log2(mean+eps), dtv/pl partials, global sums ----
        float ge2 = 0.f, gent = 0.f;
        if (tid < CC/4) {
            const float4* pb = reinterpret_cast<const float4*>(buf);
            float4 m = pb[tid];
            #pragma unroll
            for (int e = 1; e < EE; e++) {
                float4 p = pb[e*(CC/4) + tid];
                m.x += p.x; m.y += p.y; m.z += p.z; m.w += p.w;
            }
            m.x *= 0.125f; m.y *= 0.125f; m.z *= 0.125f; m.w *= 0.125f;
            float4 L;
            L.x = __log2f(m.x + FEPS);
            L.y = __log2f(m.y + FEPS);
            L.z = __log2f(m.z + FEPS);
            L.w = __log2f(m.w + FEPS);
            ge2  = m.x*m.x + m.y*m.y + m.z*m.z + m.w*m.w;
            gent = m.x*L.x + m.y*L.y + m.z*L.z + m.w*L.w;
            #pragma unroll
            for (int e = 0; e < EE; e++) {
                float4 p = pb[e*(CC/4) + tid];
                sdtv[e*256 + tid] = p.x*m.x + p.y*m.y + p.z*m.z + p.w*m.w;
                spl [e*256 + tid] = p.x*L.x + p.y*L.y + p.z*L.z + p.w*L.w;
            }
        } else {
            #pragma unroll
            for (int e = 0; e < EE; e++) {
                sdtv[e*256 + tid] = 0.f;
                spl [e*256 + tid] = 0.f;
            }
        }
        #pragma unroll
        for (int off = 16; off; off >>= 1) {
            ge2  += __shfl_xor_sync(0xffffffffu, ge2,  off);
            gent += __shfl_xor_sync(0xffffffffu, gent, off);
        }
        if (lane == 0) { s_red[wid] = ge2; s_red[8 + wid] = gent; }
        __syncthreads();
        if (tid == 0) {
            float a = 0.f, g = 0.f;
            #pragma unroll
            for (int w = 0; w < 8; w++) { a += s_red[w]; g += s_red[8 + w]; }
            s_ge2 = a; s_gent = g;
        }
        __syncthreads();

        // ---- phase 2: warp wid handles expert wid ----
        {
            const float mn = fmaxf(sqrtf(s_ge2), FEPS);
            const float4* row = reinterpret_cast<const float4*>(buf) + wid*(CC/4);

            float slp = 0.f, sq = 0.f;
            float v0 = 0.f, v1 = 0.f, v2 = 0.f, v3 = 0.f, v4 = 0.f;

            #pragma unroll
            for (int k = 0; k < 8; k++) {
                int t = lane + 32*k;
                if (t < CC/4) {
                    float4 p = row[t];
                    #define DOELEM(px)                                           \
                    {                                                            \
                        float lp = __log2f((px) + FEPS);                         \
                        slp += (px)*lp;                                          \
                        sq  += (px)*(px);                                        \
                        float t0 = fminf(v0, (px)); v0 = fmaxf(v0, (px));        \
                        float t1 = fminf(v1, t0);   v1 = fmaxf(v1, t0);          \
                        float t2 = fminf(v2, t1);   v2 = fmaxf(v2, t1);          \
                        float t3 = fminf(v3, t2);   v3 = fmaxf(v3, t2);          \
                        v4 = fmaxf(v4, t3);                                      \
                    }
                    DOELEM(p.x) DOELEM(p.y) DOELEM(p.z) DOELEM(p.w)
                    #undef DOELEM
                }
            }
            #pragma unroll
            for (int off = 16; off; off >>= 1) {
                slp += __shfl_xor_sync(0xffffffffu, slp, off);
                sq  += __shfl_xor_sync(0xffffffffu, sq,  off);
            }

            // dtv, pl from phase-1 partials (warp-local reduce of 256 floats each)
            float dtv, pl;
            {
                const float4* dp = reinterpret_cast<const float4*>(sdtv + wid*256);
                const float4* lp = reinterpret_cast<const float4*>(spl  + wid*256);
                float4 a = dp[lane], b4 = dp[lane + 32];
                float4 c = lp[lane], d4 = lp[lane + 32];
                float sd = a.x+a.y+a.z+a.w + b4.x+b4.y+b4.z+b4.w;
                float sl = c.x+c.y+c.z+c.w + d4.x+d4.y+d4.z+d4.w;
                #pragma unroll
                for (int off = 16; off; off >>= 1) {
                    sd += __shfl_xor_sync(0xffffffffu, sd, off);
                    sl += __shfl_xor_sync(0xffffffffu, sl, off);
                }
                dtv = sd; pl = sl;
            }

            // top-5 merge via REDUX.MAX on float bits (all values >= 0)
            float o0, o1, o2, o3, o4;
            #pragma unroll
            for (int r = 0; r < 5; r++) {
                unsigned myb = __float_as_uint(v0);
                unsigned mxb = __reduce_max_sync(0xffffffffu, myb);
                unsigned msk = __ballot_sync(0xffffffffu, myb == mxb);
                if (lane == __ffs(msk) - 1) { v0 = v1; v1 = v2; v2 = v3; v3 = v4; v4 = 0.f; }
                float mx = __uint_as_float(mxb);
                if (r == 0) o0 = mx; else if (r == 1) o1 = mx;
                else if (r == 2) o2 = mx; else if (r == 3) o3 = mx; else o4 = mx;
            }

            if (lane == 0) {
                float ent  = -slp * LN2F;
                float mass = o0 + o1 + o2 + o3 + o4;
                float pn   = fmaxf(sqrtf(sq), FEPS);
                s_feat[0*EE + wid] = ent;
                s_feat[1*EE + wid] = mass;
                s_feat[2*EE + wid] = 1.f - mass;
                s_feat[3*EE + wid] = o0;
                s_feat[4*EE + wid] = o0 - o1;
                s_feat[5*EE + wid] = dtv / (pn * mn);
                s_feat[6*EE + wid] = (slp - pl) * LN2F;
                s_sq[wid] = sq;
            }
        }
        __syncthreads();

        if (tid == 0) {
            float totsq = 0.f;
            #pragma unroll
            for (int e = 0; e < EE; e++) totsq += s_sq[e];
            float mcv = (totsq - 8.f * s_ge2) * (1.f / 7000.f);
            float mu = 0.f;
            #pragma unroll
            for (int e = 0; e < EE; e++) mu += s_feat[3*EE + e];
            mu *= 0.125f;
            float var = 0.f;
            #pragma unroll
            for (int e = 0; e < EE; e++) {
                float d = s_feat[3*EE + e] - mu;
                var += d * d;
            }
            s_feat[56] = -s_gent * LN2F;
            s_feat[57] = mcv;
            s_feat[58] = sqrtf(var * (1.f/7.f));
        }
        __syncthreads();

        if (tid < DD) {
            float v = s_feat[tid];
            v = fminf(fmaxf(v, -100.f), 100.f);
            feats[(size_t)b * DD + tid] = v;
        }
        __syncthreads();   // buf reads done before next item's cp.async
    }
}

// ---------------------------------------------------------------------------
// Kernel B: MLP. Exact copy of the R2/R4 version (measured 118.7us).
// ---------------------------------------------------------------------------
#define MROWS  4
#define GROUPS 2

__global__ void __launch_bounds__(512) mlp_kernel(
    const float* __restrict__ feats,
    const float* __restrict__ W1, const float* __restrict__ b1,
    const float* __restrict__ g1, const float* __restrict__ be1,
    const float* __restrict__ W2, const float* __restrict__ b2,
    const float* __restrict__ g2, const float* __restrict__ be2,
    const float* __restrict__ W3, const float* __restrict__ b3,
    float* __restrict__ wout, float* __restrict__ lout)
{
    extern __shared__ float sm[];
    float* sW1  = sm;                        // 59*256 = 15104
    float* sW3  = sW1  + DD*HH1;             // 128*8  = 1024
    float* sb1  = sW3  + HH2*EE;             // 256
    float* sg1  = sb1  + HH1;
    float* sbe1 = sg1  + HH1;
    float* sb2  = sbe1 + HH1;                // 128
    float* sg2  = sb2  + HH2;
    float* sbe2 = sg2  + HH2;
    float* sb3  = sbe2 + HH2;                // 8
    float* sf   = sb3  + EE;                 // 8*59   = 472
    float* sh1  = sf   + GROUPS*MROWS*DD;    // 8*256  = 2048
    float* sh2  = sh1  + GROUPS*MROWS*HH1;   // 8*128  = 1024
    float* spart= sh2  + GROUPS*MROWS*HH2;   // 2*1024 = 2048
    float* slog = spart+ GROUPS*2*HH2*MROWS; // 64
    float* sred = slog + GROUPS*MROWS*EE;    // 128
    float* smu  = sred + 128;                // 8
    float* srs  = smu  + GROUPS*MROWS;       // 8

    const int tid  = threadIdx.x;
    const int lane = tid & 31;
    const int wid  = tid >> 5;
    const int g    = tid >> 8;
    const int gtid = tid & 255;

    for (int i = tid; i < DD*HH1;  i += 512) sW1[i] = W1[i];
    for (int i = tid; i < HH2*EE;  i += 512) sW3[i] = W3[i];
    for (int i = tid; i < HH1;     i += 512) { sb1[i] = b1[i]; sg1[i] = g1[i]; sbe1[i] = be1[i]; }
    for (int i = tid; i < HH2;     i += 512) { sb2[i] = b2[i]; sg2[i] = g2[i]; sbe2[i] = be2[i]; }
    if (tid < EE) sb3[tid] = b3[tid];
    __syncthreads();

    const int RPC = GROUPS * MROWS;
    const int nchunks = BB / RPC;
    for (int chunk = blockIdx.x; chunk < nchunks; chunk += gridDim.x) {
        const int row0 = chunk * RPC;

        for (int i = tid; i < RPC*DD; i += 512)
            sf[i] = feats[(size_t)row0 * DD + i];
        __syncthreads();

        // ---- layer 1: 59 -> 256 ----
        float acc[MROWS];
        {
            const int j = gtid;
            #pragma unroll
            for (int r = 0; r < MROWS; r++) acc[r] = sb1[j];
            for (int i = 0; i < DD; i++) {
                float w = sW1[i*HH1 + j];
                #pragma unroll
                for (int r = 0; r < MROWS; r++) acc[r] += sf[(g*MROWS + r)*DD + i] * w;
            }
        }
        {
            float sv[MROWS], sq2[MROWS];
            #pragma unroll
            for (int r = 0; r < MROWS; r++) { sv[r] = acc[r]; sq2[r] = acc[r]*acc[r]; }
            #pragma unroll
            for (int off = 16; off; off >>= 1) {
                #pragma unroll
                for (int r = 0; r < MROWS; r++) {
                    sv[r]  += __shfl_xor_sync(0xffffffffu, sv[r],  off);
                    sq2[r] += __shfl_xor_sync(0xffffffffu, sq2[r], off);
                }
            }
            if (lane == 0) {
                #pragma unroll
                for (int r = 0; r < MROWS; r++) {
                    sred[wid*4 + r]      = sv[r];
                    sred[64 + wid*4 + r] = sq2[r];
                }
            }
        }
        __syncthreads();
        if (tid < RPC) {
            const int gg = tid >> 2;
            float a = 0.f, q = 0.f;
            #pragma unroll
            for (int w = 0; w < 8; w++) {
                a += sred[(gg*8 + w)*4 + (tid & 3)];
                q += sred[64 + (gg*8 + w)*4 + (tid & 3)];
            }
            float mu  = a * (1.f/256.f);
            float var = q * (1.f/256.f) - mu*mu;
            smu[tid] = mu;
            srs[tid] = rsqrtf(var + LNEPS);
        }
        __syncthreads();
        {
            const int j = gtid;
            #pragma unroll
            for (int r = 0; r < MROWS; r++) {
                float h = (acc[r] - smu[g*MROWS + r]) * srs[g*MROWS + r] * sg1[j] + sbe1[j];
                sh1[(g*MROWS + r)*HH1 + j] = fmaxf(h, 0.f);
            }
        }
        __syncthreads();

        // ---- layer 2: 256 -> 128, W2 from L2, split-K=2 ----
        {
            const int j    = gtid & (HH2 - 1);
            const int half = gtid >> 7;
            float a2[MROWS];
            #pragma unroll
            for (int r = 0; r < MROWS; r++) a2[r] = 0.f;
            const int i0 = half * 128;
            #pragma unroll 4
            for (int i = i0; i < i0 + 128; i++) {
                float w = __ldg(&W2[i*HH2 + j]);
                #pragma unroll
                for (int r = 0; r < MROWS; r++) a2[r] += sh1[(g*MROWS + r)*HH1 + i] * w;
            }
            #pragma unroll
            for (int r = 0; r < MROWS; r++)
                spart[g*(2*HH2*MROWS) + (half*HH2 + j)*MROWS + r] = a2[r];
        }
        __syncthreads();
        float acc3[MROWS];
        if (gtid < HH2) {
            const int j = gtid;
            #pragma unroll
            for (int r = 0; r < MROWS; r++)
                acc3[r] = spart[g*(2*HH2*MROWS) + j*MROWS + r]
                        + spart[g*(2*HH2*MROWS) + (HH2 + j)*MROWS + r] + sb2[j];
            float sv[MROWS], sq2[MROWS];
            #pragma unroll
            for (int r = 0; r < MROWS; r++) { sv[r] = acc3[r]; sq2[r] = acc3[r]*acc3[r]; }
            #pragma unroll
            for (int off = 16; off; off >>= 1) {
                #pragma unroll
                for (int r = 0; r < MROWS; r++) {
                    sv[r]  += __shfl_xor_sync(0xffffffffu, sv[r],  off);
                    sq2[r] += __shfl_xor_sync(0xffffffffu, sq2[r], off);
                }
            }
            if (lane == 0) {
                #pragma unroll
                for (int r = 0; r < MROWS; r++) {
                    sred[wid*4 + r]      = sv[r];
                    sred[64 + wid*4 + r] = sq2[r];
                }
            }
        }
        __syncthreads();
        if (tid < RPC) {
            const int gg = tid >> 2;
            float a = 0.f, q = 0.f;
            #pragma unroll
            for (int w = 0; w < 4; w++) {
                a += sred[(gg*8 + w)*4 + (tid & 3)];
                q += sred[64 + (gg*8 + w)*4 + (tid & 3)];
            }
            float mu  = a * (1.f/128.f);
            float var = q * (1.f/128.f) - mu*mu;
            smu[tid] = mu;
            srs[tid] = rsqrtf(var + LNEPS);
        }
        __syncthreads();
        if (gtid < HH2) {
            #pragma unroll
            for (int r = 0; r < MROWS; r++) {
                float h = (acc3[r] - smu[g*MROWS + r]) * srs[g*MROWS + r] * sg2[gtid] + sbe2[gtid];
                sh2[(g*MROWS + r)*HH2 + gtid] = fmaxf(h, 0.f);
            }
        }
        __syncthreads();

        // ---- layer 3 + softmax ----
        if (tid < RPC*EE) {
            const int r = tid >> 3;
            const int o = tid & 7;
            float a = sb3[o];
            #pragma unroll 8
            for (int i = 0; i < HH2; i++) a += sh2[r*HH2 + i] * sW3[i*EE + o];
            slog[r*EE + o] = a;

            float mx = a;
            #pragma unroll
            for (int off = 4; off; off >>= 1)
                mx = fmaxf(mx, __shfl_xor_sync(0xffffffffu, mx, off));
            float ex = __expf(a - mx);
            float sme = ex;
            #pragma unroll
            for (int off = 4; off; off >>= 1)
                sme += __shfl_xor_sync(0xffffffffu, sme, off);
            const int row = row0 + r;
            lout[(size_t)row*EE + o] = a;
            wout[(size_t)row*EE + o] = ex / sme;
        }
        __syncthreads();
    }
}

// ---------------------------------------------------------------------------
extern "C" void kernel_launch(void* const* d_in, const int* in_sizes, int n_in,
                              void* d_out, int out_size)
{
    (void)in_sizes; (void)n_in; (void)out_size;
    const float* P   = (const float*)d_in[0];
    const float* W1  = (const float*)d_in[1];
    const float* b1  = (const float*)d_in[2];
    const float* g1  = (const float*)d_in[3];
    const float* be1 = (const float*)d_in[4];
    const float* W2  = (const float*)d_in[5];
    const float* b2  = (const float*)d_in[6];
    const float* g2  = (const float*)d_in[7];
    const float* be2 = (const float*)d_in[8];
    const float* W3  = (const float*)d_in[9];
    const float* b3  = (const float*)d_in[10];

    float* out   = (float*)d_out;
    float* wout  = out;                    // weights: B*8
    float* lout  = out + (size_t)BB*EE;    // logits:  B*8
    float* feats = out + (size_t)2*BB*EE;  // feats:   B*59

    const size_t smemA = (size_t)(EE*CC + 2*8*256) * sizeof(float);  // 48384 B
    cudaFuncSetAttribute(feat_kernel, cudaFuncAttributeMaxDynamicSharedMemorySize, (int)smemA);
    feat_kernel<<<592, 256, smemA>>>(P, feats);

    const size_t smemB = (size_t)(DD*HH1 + HH2*EE
                                  + 3*HH1 + 3*HH2 + EE
                                  + GROUPS*MROWS*DD + GROUPS*MROWS*HH1 + GROUPS*MROWS*HH2
                                  + GROUPS*2*HH2*MROWS + GROUPS*MROWS*EE + 128 + 16)
                         * sizeof(float);
    cudaFuncSetAttribute(mlp_kernel, cudaFuncAttributeMaxDynamicSharedMemorySize, (int)smemB);
    mlp_kernel<<<296, 512, smemB>>>(feats, W1, b1, g1, be1, W2, b2, g2, be2, W3, b3,
                                    wout, lout);
}

// round 7
// speedup vs baseline: 1.5954x; 1.0049x over previous
#include <cuda_runtime.h>
#include <math.h>

#define BB   16384
#define EE   8
#define CC   1000
#define DD   59
#define HH1  256
#define HH2  128
#define FEPS 1e-8f
#define LNEPS 1e-5f
#define LN2F 0.69314718055994530942f

// ---------------------------------------------------------------------------
__device__ __forceinline__ void cp_async16(void* smem_ptr, const void* gmem) {
    unsigned s = (unsigned)__cvta_generic_to_shared(smem_ptr);
    asm volatile("cp.async.cg.shared.global [%0], [%1], 16;\n" :: "r"(s), "l"(gmem));
}
#define CP_COMMIT() asm volatile("cp.async.commit_group;\n" ::: "memory")
#define CP_WAIT0()  asm volatile("cp.async.wait_group 0;\n" ::: "memory")

// ---------------------------------------------------------------------------
// Kernel A: feature extraction. 256 thr/block, single buffer, 4 blocks/SM.
// dyn smem: buf[8000] + sdtv[8*256] + spl[8*256] = 48384 B
// ---------------------------------------------------------------------------
__global__ void __launch_bounds__(256, 4) feat_kernel(const float* __restrict__ P,
                                                      float* __restrict__ feats)
{
    extern __shared__ float dyn[];
    float* buf  = dyn;             // 8000
    float* sdtv = dyn + 8000;      // 8*256
    float* spl  = sdtv + 8*256;    // 8*256

    __shared__ float s_feat[64];
    __shared__ float s_sq[EE];
    __shared__ float s_red[16];
    __shared__ float s_ge2, s_gent;

    const int tid  = threadIdx.x;
    const int lane = tid & 31;
    const int wid  = tid >> 5;

    for (int b = blockIdx.x; b < BB; b += gridDim.x) {
        // ---- stage item into smem ----
        {
            const float4* src = reinterpret_cast<const float4*>(P + (size_t)b*(EE*CC));
            float4* dst = reinterpret_cast<float4*>(buf);
            for (int i = tid; i < EE*CC/4; i += 256) cp_async16(&dst[i], &src[i]);
        }
        CP_COMMIT();
        CP_WAIT0();
        __syncthreads();

        // ---- phase 1: mean, log2(mean+eps), dtv/pl partials, global sums ----
        float ge2 = 0.f, gent = 0.f;
        if (tid < CC/4) {
            const float4* pb = reinterpret_cast<const float4*>(buf);
            float4 m = pb[tid];
            #pragma unroll
            for (int e = 1; e < EE; e++) {
                float4 p = pb[e*(CC/4) + tid];
                m.x += p.x; m.y += p.y; m.z += p.z; m.w += p.w;
            }
            m.x *= 0.125f; m.y *= 0.125f; m.z *= 0.125f; m.w *= 0.125f;
            float4 L;
            L.x = __log2f(m.x + FEPS);
            L.y = __log2f(m.y + FEPS);
            L.z = __log2f(m.z + FEPS);
            L.w = __log2f(m.w + FEPS);
            ge2  = m.x*m.x + m.y*m.y + m.z*m.z + m.w*m.w;
            gent = m.x*L.x + m.y*L.y + m.z*L.z + m.w*L.w;
            #pragma unroll
            for (int e = 0; e < EE; e++) {
                float4 p = pb[e*(CC/4) + tid];
                sdtv[e*256 + tid] = p.x*m.x + p.y*m.y + p.z*m.z + p.w*m.w;
                spl [e*256 + tid] = p.x*L.x + p.y*L.y + p.z*L.z + p.w*L.w;
            }
        } else {
            #pragma unroll
            for (int e = 0; e < EE; e++) {
                sdtv[e*256 + tid] = 0.f;
                spl [e*256 + tid] = 0.f;
            }
        }
        #pragma unroll
        for (int off = 16; off; off >>= 1) {
            ge2  += __shfl_xor_sync(0xffffffffu, ge2,  off);
            gent += __shfl_xor_sync(0xffffffffu, gent, off);
        }
        if (lane == 0) { s_red[wid] = ge2; s_red[8 + wid] = gent; }
        __syncthreads();
        if (tid == 0) {
            float a = 0.f, g = 0.f;
            #pragma unroll
            for (int w = 0; w < 8; w++) { a += s_red[w]; g += s_red[8 + w]; }
            s_ge2 = a; s_gent = g;
        }
        __syncthreads();

        // ---- phase 2: warp wid handles expert wid ----
        {
            const float mn = fmaxf(sqrtf(s_ge2), FEPS);
            const float4* row = reinterpret_cast<const float4*>(buf) + wid*(CC/4);

            float slp = 0.f, sq = 0.f;
            float v0 = 0.f, v1 = 0.f, v2 = 0.f, v3 = 0.f, v4 = 0.f;

            #pragma unroll
            for (int k = 0; k < 8; k++) {
                int t = lane + 32*k;
                if (t < CC/4) {
                    float4 p = row[t];
                    #define DOELEM(px)                                           \
                    {                                                            \
                        float lp = __log2f((px) + FEPS);                         \
                        slp += (px)*lp;                                          \
                        sq  += (px)*(px);                                        \
                        float t0 = fminf(v0, (px)); v0 = fmaxf(v0, (px));        \
                        float t1 = fminf(v1, t0);   v1 = fmaxf(v1, t0);          \
                        float t2 = fminf(v2, t1);   v2 = fmaxf(v2, t1);          \
                        float t3 = fminf(v3, t2);   v3 = fmaxf(v3, t2);          \
                        v4 = fmaxf(v4, t3);                                      \
                    }
                    DOELEM(p.x) DOELEM(p.y) DOELEM(p.z) DOELEM(p.w)
                    #undef DOELEM
                }
            }
            #pragma unroll
            for (int off = 16; off; off >>= 1) {
                slp += __shfl_xor_sync(0xffffffffu, slp, off);
                sq  += __shfl_xor_sync(0xffffffffu, sq,  off);
            }

            // dtv, pl from phase-1 partials (warp-local reduce of 256 floats each)
            float dtv, pl;
            {
                const float4* dp = reinterpret_cast<const float4*>(sdtv + wid*256);
                const float4* lp = reinterpret_cast<const float4*>(spl  + wid*256);
                float4 a = dp[lane], b4 = dp[lane + 32];
                float4 c = lp[lane], d4 = lp[lane + 32];
                float sd = a.x+a.y+a.z+a.w + b4.x+b4.y+b4.z+b4.w;
                float sl = c.x+c.y+c.z+c.w + d4.x+d4.y+d4.z+d4.w;
                #pragma unroll
                for (int off = 16; off; off >>= 1) {
                    sd += __shfl_xor_sync(0xffffffffu, sd, off);
                    sl += __shfl_xor_sync(0xffffffffu, sl, off);
                }
                dtv = sd; pl = sl;
            }

            // top-5 merge via REDUX.MAX on float bits (all values >= 0)
            float o0, o1, o2, o3, o4;
            #pragma unroll
            for (int r = 0; r < 5; r++) {
                unsigned myb = __float_as_uint(v0);
                unsigned mxb = __reduce_max_sync(0xffffffffu, myb);
                unsigned msk = __ballot_sync(0xffffffffu, myb == mxb);
                if (lane == __ffs(msk) - 1) { v0 = v1; v1 = v2; v2 = v3; v3 = v4; v4 = 0.f; }
                float mx = __uint_as_float(mxb);
                if (r == 0) o0 = mx; else if (r == 1) o1 = mx;
                else if (r == 2) o2 = mx; else if (r == 3) o3 = mx; else o4 = mx;
            }

            if (lane == 0) {
                float ent  = -slp * LN2F;
                float mass = o0 + o1 + o2 + o3 + o4;
                float pn   = fmaxf(sqrtf(sq), FEPS);
                s_feat[0*EE + wid] = ent;
                s_feat[1*EE + wid] = mass;
                s_feat[2*EE + wid] = 1.f - mass;
                s_feat[3*EE + wid] = o0;
                s_feat[4*EE + wid] = o0 - o1;
                s_feat[5*EE + wid] = dtv / (pn * mn);
                s_feat[6*EE + wid] = (slp - pl) * LN2F;
                s_sq[wid] = sq;
            }
        }
        __syncthreads();

        if (tid == 0) {
            float totsq = 0.f;
            #pragma unroll
            for (int e = 0; e < EE; e++) totsq += s_sq[e];
            float mcv = (totsq - 8.f * s_ge2) * (1.f / 7000.f);
            float mu = 0.f;
            #pragma unroll
            for (int e = 0; e < EE; e++) mu += s_feat[3*EE + e];
            mu *= 0.125f;
            float var = 0.f;
            #pragma unroll
            for (int e = 0; e < EE; e++) {
                float d = s_feat[3*EE + e] - mu;
                var += d * d;
            }
            s_feat[56] = -s_gent * LN2F;
            s_feat[57] = mcv;
            s_feat[58] = sqrtf(var * (1.f/7.f));
        }
        __syncthreads();

        if (tid < DD) {
            float v = s_feat[tid];
            v = fminf(fmaxf(v, -100.f), 100.f);
            feats[(size_t)b * DD + tid] = v;
        }
        __syncthreads();   // buf reads done before next item's cp.async
    }
}

// ---------------------------------------------------------------------------
// Kernel B: MLP. Exact copy of the R2/R4 version (measured 118.7us).
// ---------------------------------------------------------------------------
#define MROWS  4
#define GROUPS 2

__global__ void __launch_bounds__(512) mlp_kernel(
    const float* __restrict__ feats,
    const float* __restrict__ W1, const float* __restrict__ b1,
    const float* __restrict__ g1, const float* __restrict__ be1,
    const float* __restrict__ W2, const float* __restrict__ b2,
    const float* __restrict__ g2, const float* __restrict__ be2,
    const float* __restrict__ W3, const float* __restrict__ b3,
    float* __restrict__ wout, float* __restrict__ lout)
{
    extern __shared__ float sm[];
    float* sW1  = sm;                        // 59*256 = 15104
    float* sW3  = sW1  + DD*HH1;             // 128*8  = 1024
    float* sb1  = sW3  + HH2*EE;             // 256
    float* sg1  = sb1  + HH1;
    float* sbe1 = sg1  + HH1;
    float* sb2  = sbe1 + HH1;                // 128
    float* sg2  = sb2  + HH2;
    float* sbe2 = sg2  + HH2;
    float* sb3  = sbe2 + HH2;                // 8
    float* sf   = sb3  + EE;                 // 8*59   = 472
    float* sh1  = sf   + GROUPS*MROWS*DD;    // 8*256  = 2048
    float* sh2  = sh1  + GROUPS*MROWS*HH1;   // 8*128  = 1024
    float* spart= sh2  + GROUPS*MROWS*HH2;   // 2*1024 = 2048
    float* slog = spart+ GROUPS*2*HH2*MROWS; // 64
    float* sred = slog + GROUPS*MROWS*EE;    // 128
    float* smu  = sred + 128;                // 8
    float* srs  = smu  + GROUPS*MROWS;       // 8

    const int tid  = threadIdx.x;
    const int lane = tid & 31;
    const int wid  = tid >> 5;
    const int g    = tid >> 8;
    const int gtid = tid & 255;

    for (int i = tid; i < DD*HH1;  i += 512) sW1[i] = W1[i];
    for (int i = tid; i < HH2*EE;  i += 512) sW3[i] = W3[i];
    for (int i = tid; i < HH1;     i += 512) { sb1[i] = b1[i]; sg1[i] = g1[i]; sbe1[i] = be1[i]; }
    for (int i = tid; i < HH2;     i += 512) { sb2[i] = b2[i]; sg2[i] = g2[i]; sbe2[i] = be2[i]; }
    if (tid < EE) sb3[tid] = b3[tid];
    __syncthreads();

    const int RPC = GROUPS * MROWS;
    const int nchunks = BB / RPC;
    for (int chunk = blockIdx.x; chunk < nchunks; chunk += gridDim.x) {
        const int row0 = chunk * RPC;

        for (int i = tid; i < RPC*DD; i += 512)
            sf[i] = feats[(size_t)row0 * DD + i];
        __syncthreads();

        // ---- layer 1: 59 -> 256 ----
        float acc[MROWS];
        {
            const int j = gtid;
            #pragma unroll
            for (int r = 0; r < MROWS; r++) acc[r] = sb1[j];
            for (int i = 0; i < DD; i++) {
                float w = sW1[i*HH1 + j];
                #pragma unroll
                for (int r = 0; r < MROWS; r++) acc[r] += sf[(g*MROWS + r)*DD + i] * w;
            }
        }
        {
            float sv[MROWS], sq2[MROWS];
            #pragma unroll
            for (int r = 0; r < MROWS; r++) { sv[r] = acc[r]; sq2[r] = acc[r]*acc[r]; }
            #pragma unroll
            for (int off = 16; off; off >>= 1) {
                #pragma unroll
                for (int r = 0; r < MROWS; r++) {
                    sv[r]  += __shfl_xor_sync(0xffffffffu, sv[r],  off);
                    sq2[r] += __shfl_xor_sync(0xffffffffu, sq2[r], off);
                }
            }
            if (lane == 0) {
                #pragma unroll
                for (int r = 0; r < MROWS; r++) {
                    sred[wid*4 + r]      = sv[r];
                    sred[64 + wid*4 + r] = sq2[r];
                }
            }
        }
        __syncthreads();
        if (tid < RPC) {
            const int gg = tid >> 2;
            float a = 0.f, q = 0.f;
            #pragma unroll
            for (int w = 0; w < 8; w++) {
                a += sred[(gg*8 + w)*4 + (tid & 3)];
                q += sred[64 + (gg*8 + w)*4 + (tid & 3)];
            }
            float mu  = a * (1.f/256.f);
            float var = q * (1.f/256.f) - mu*mu;
            smu[tid] = mu;
            srs[tid] = rsqrtf(var + LNEPS);
        }
        __syncthreads();
        {
            const int j = gtid;
            #pragma unroll
            for (int r = 0; r < MROWS; r++) {
                float h = (acc[r] - smu[g*MROWS + r]) * srs[g*MROWS + r] * sg1[j] + sbe1[j];
                sh1[(g*MROWS + r)*HH1 + j] = fmaxf(h, 0.f);
            }
        }
        __syncthreads();

        // ---- layer 2: 256 -> 128, W2 from L2, split-K=2 ----
        {
            const int j    = gtid & (HH2 - 1);
            const int half = gtid >> 7;
            float a2[MROWS];
            #pragma unroll
            for (int r = 0; r < MROWS; r++) a2[r] = 0.f;
            const int i0 = half * 128;
            #pragma unroll 4
            for (int i = i0; i < i0 + 128; i++) {
                float w = __ldg(&W2[i*HH2 + j]);
                #pragma unroll
                for (int r = 0; r < MROWS; r++) a2[r] += sh1[(g*MROWS + r)*HH1 + i] * w;
            }
            #pragma unroll
            for (int r = 0; r < MROWS; r++)
                spart[g*(2*HH2*MROWS) + (half*HH2 + j)*MROWS + r] = a2[r];
        }
        __syncthreads();
        float acc3[MROWS];
        if (gtid < HH2) {
            const int j = gtid;
            #pragma unroll
            for (int r = 0; r < MROWS; r++)
                acc3[r] = spart[g*(2*HH2*MROWS) + j*MROWS + r]
                        + spart[g*(2*HH2*MROWS) + (HH2 + j)*MROWS + r] + sb2[j];
            float sv[MROWS], sq2[MROWS];
            #pragma unroll
            for (int r = 0; r < MROWS; r++) { sv[r] = acc3[r]; sq2[r] = acc3[r]*acc3[r]; }
            #pragma unroll
            for (int off = 16; off; off >>= 1) {
                #pragma unroll
                for (int r = 0; r < MROWS; r++) {
                    sv[r]  += __shfl_xor_sync(0xffffffffu, sv[r],  off);
                    sq2[r] += __shfl_xor_sync(0xffffffffu, sq2[r], off);
                }
            }
            if (lane == 0) {
                #pragma unroll
                for (int r = 0; r < MROWS; r++) {
                    sred[wid*4 + r]      = sv[r];
                    sred[64 + wid*4 + r] = sq2[r];
                }
            }
        }
        __syncthreads();
        if (tid < RPC) {
            const int gg = tid >> 2;
            float a = 0.f, q = 0.f;
            #pragma unroll
            for (int w = 0; w < 4; w++) {
                a += sred[(gg*8 + w)*4 + (tid & 3)];
                q += sred[64 + (gg*8 + w)*4 + (tid & 3)];
            }
            float mu  = a * (1.f/128.f);
            float var = q * (1.f/128.f) - mu*mu;
            smu[tid] = mu;
            srs[tid] = rsqrtf(var + LNEPS);
        }
        __syncthreads();
        if (gtid < HH2) {
            #pragma unroll
            for (int r = 0; r < MROWS; r++) {
                float h = (acc3[r] - smu[g*MROWS + r]) * srs[g*MROWS + r] * sg2[gtid] + sbe2[gtid];
                sh2[(g*MROWS + r)*HH2 + gtid] = fmaxf(h, 0.f);
            }
        }
        __syncthreads();

        // ---- layer 3 + softmax ----
        if (tid < RPC*EE) {
            const int r = tid >> 3;
            const int o = tid & 7;
            float a = sb3[o];
            #pragma unroll 8
            for (int i = 0; i < HH2; i++) a += sh2[r*HH2 + i] * sW3[i*EE + o];
            slog[r*EE + o] = a;

            float mx = a;
            #pragma unroll
            for (int off = 4; off; off >>= 1)
                mx = fmaxf(mx, __shfl_xor_sync(0xffffffffu, mx, off));
            float ex = __expf(a - mx);
            float sme = ex;
            #pragma unroll
            for (int off = 4; off; off >>= 1)
                sme += __shfl_xor_sync(0xffffffffu, sme, off);
            const int row = row0 + r;
            lout[(size_t)row*EE + o] = a;
            wout[(size_t)row*EE + o] = ex / sme;
        }
        __syncthreads();
    }
}

// ---------------------------------------------------------------------------
extern "C" void kernel_launch(void* const* d_in, const int* in_sizes, int n_in,
                              void* d_out, int out_size)
{
    (void)in_sizes; (void)n_in; (void)out_size;
    const float* P   = (const float*)d_in[0];
    const float* W1  = (const float*)d_in[1];
    const float* b1  = (const float*)d_in[2];
    const float* g1  = (const float*)d_in[3];
    const float* be1 = (const float*)d_in[4];
    const float* W2  = (const float*)d_in[5];
    const float* b2  = (const float*)d_in[6];
    const float* g2  = (const float*)d_in[7];
    const float* be2 = (const float*)d_in[8];
    const float* W3  = (const float*)d_in[9];
    const float* b3  = (const float*)d_in[10];

    float* out   = (float*)d_out;
    float* wout  = out;                    // weights: B*8
    float* lout  = out + (size_t)BB*EE;    // logits:  B*8
    float* feats = out + (size_t)2*BB*EE;  // feats:   B*59

    const size_t smemA = (size_t)(EE*CC + 2*8*256) * sizeof(float);  // 48384 B
    cudaFuncSetAttribute(feat_kernel, cudaFuncAttributeMaxDynamicSharedMemorySize, (int)smemA);
    feat_kernel<<<592, 256, smemA>>>(P, feats);

    const size_t smemB = (size_t)(DD*HH1 + HH2*EE
                                  + 3*HH1 + 3*HH2 + EE
                                  + GROUPS*MROWS*DD + GROUPS*MROWS*HH1 + GROUPS*MROWS*HH2
                                  + GROUPS*2*HH2*MROWS + GROUPS*MROWS*EE + 128 + 16)
                         * sizeof(float);
    cudaFuncSetAttribute(mlp_kernel, cudaFuncAttributeMaxDynamicSharedMemorySize, (int)smemB);
    mlp_kernel<<<296, 512, smemB>>>(feats, W1, b1, g1, be1, W2, b2, g2, be2, W3, b3,
                                    wout, lout);
}

// round 8
// speedup vs baseline: 1.7701x; 1.1095x over previous
#include <cuda_runtime.h>
#include <math.h>

#define BB   16384
#define EE   8
#define CC   1000
#define DD   59
#define HH1  256
#define HH2  128
#define FEPS 1e-8f
#define LNEPS 1e-5f
#define LN2F 0.69314718055994530942f

// ---------------------------------------------------------------------------
__device__ __forceinline__ void cp_async16(void* smem_ptr, const void* gmem) {
    unsigned s = (unsigned)__cvta_generic_to_shared(smem_ptr);
    asm volatile("cp.async.cg.shared.global [%0], [%1], 16;\n" :: "r"(s), "l"(gmem));
}
#define CP_COMMIT() asm volatile("cp.async.commit_group;\n" ::: "memory")
#define CP_WAIT0()  asm volatile("cp.async.wait_group 0;\n" ::: "memory")

// ---------------------------------------------------------------------------
// Kernel A: feature extraction. 256 thr/block, 4 blocks/SM.
// Phase 1 reads each expert float4 ONCE into registers (8 LDS.128, not 24).
// dyn smem: buf[8000] + sdtv[2048] + spl[2048] = 48384 B
// ---------------------------------------------------------------------------
__global__ void __launch_bounds__(256, 4) feat_kernel(const float* __restrict__ P,
                                                      float* __restrict__ feats)
{
    extern __shared__ float dyn[];
    float* buf  = dyn;             // 8000
    float* sdtv = dyn + 8000;      // 8*256
    float* spl  = sdtv + 8*256;    // 8*256

    __shared__ float s_feat[64];
    __shared__ float s_sq[EE];
    __shared__ float s_red[16];
    __shared__ float s_ge2, s_gent;

    const int tid  = threadIdx.x;
    const int lane = tid & 31;
    const int wid  = tid >> 5;

    for (int b = blockIdx.x; b < BB; b += gridDim.x) {
        // ---- stage item into smem ----
        {
            const float4* src = reinterpret_cast<const float4*>(P + (size_t)b*(EE*CC));
            float4* dst = reinterpret_cast<float4*>(buf);
            for (int i = tid; i < EE*CC/4; i += 256) cp_async16(&dst[i], &src[i]);
        }
        CP_COMMIT();
        CP_WAIT0();
        __syncthreads();

        // ---- phase 1: single-read of 8 expert float4s; mean/L/dtv/pl ----
        float ge2 = 0.f, gent = 0.f;
        if (tid < CC/4) {
            const float4* pb = reinterpret_cast<const float4*>(buf);
            float4 pv[EE];
            #pragma unroll
            for (int e = 0; e < EE; e++) pv[e] = pb[e*(CC/4) + tid];
            float4 m = pv[0];
            #pragma unroll
            for (int e = 1; e < EE; e++) {
                m.x += pv[e].x; m.y += pv[e].y; m.z += pv[e].z; m.w += pv[e].w;
            }
            m.x *= 0.125f; m.y *= 0.125f; m.z *= 0.125f; m.w *= 0.125f;
            float4 L;
            L.x = __log2f(m.x + FEPS);
            L.y = __log2f(m.y + FEPS);
            L.z = __log2f(m.z + FEPS);
            L.w = __log2f(m.w + FEPS);
            ge2  = m.x*m.x + m.y*m.y + m.z*m.z + m.w*m.w;
            gent = m.x*L.x + m.y*L.y + m.z*L.z + m.w*L.w;
            #pragma unroll
            for (int e = 0; e < EE; e++) {
                sdtv[e*256 + tid] = pv[e].x*m.x + pv[e].y*m.y + pv[e].z*m.z + pv[e].w*m.w;
                spl [e*256 + tid] = pv[e].x*L.x + pv[e].y*L.y + pv[e].z*L.z + pv[e].w*L.w;
            }
        } else {
            #pragma unroll
            for (int e = 0; e < EE; e++) {
                sdtv[e*256 + tid] = 0.f;
                spl [e*256 + tid] = 0.f;
            }
        }
        #pragma unroll
        for (int off = 16; off; off >>= 1) {
            ge2  += __shfl_xor_sync(0xffffffffu, ge2,  off);
            gent += __shfl_xor_sync(0xffffffffu, gent, off);
        }
        if (lane == 0) { s_red[wid] = ge2; s_red[8 + wid] = gent; }
        __syncthreads();
        if (tid == 0) {
            float a = 0.f, g = 0.f;
            #pragma unroll
            for (int w = 0; w < 8; w++) { a += s_red[w]; g += s_red[8 + w]; }
            s_ge2 = a; s_gent = g;
        }
        __syncthreads();

        // ---- phase 2: warp wid handles expert wid ----
        {
            const float mn = fmaxf(sqrtf(s_ge2), FEPS);
            const float4* row = reinterpret_cast<const float4*>(buf) + wid*(CC/4);

            float slp = 0.f, sq = 0.f;
            float v0 = 0.f, v1 = 0.f, v2 = 0.f, v3 = 0.f, v4 = 0.f;

            #pragma unroll
            for (int k = 0; k < 8; k++) {
                int t = lane + 32*k;
                if (t < CC/4) {
                    float4 p = row[t];
                    #define DOELEM(px)                                           \
                    {                                                            \
                        float lp = __log2f((px) + FEPS);                         \
                        slp += (px)*lp;                                          \
                        sq  += (px)*(px);                                        \
                        float t0 = fminf(v0, (px)); v0 = fmaxf(v0, (px));        \
                        float t1 = fminf(v1, t0);   v1 = fmaxf(v1, t0);          \
                        float t2 = fminf(v2, t1);   v2 = fmaxf(v2, t1);          \
                        float t3 = fminf(v3, t2);   v3 = fmaxf(v3, t2);          \
                        v4 = fmaxf(v4, t3);                                      \
                    }
                    DOELEM(p.x) DOELEM(p.y) DOELEM(p.z) DOELEM(p.w)
                    #undef DOELEM
                }
            }
            #pragma unroll
            for (int off = 16; off; off >>= 1) {
                slp += __shfl_xor_sync(0xffffffffu, slp, off);
                sq  += __shfl_xor_sync(0xffffffffu, sq,  off);
            }

            float dtv, pl;
            {
                const float4* dp = reinterpret_cast<const float4*>(sdtv + wid*256);
                const float4* lp = reinterpret_cast<const float4*>(spl  + wid*256);
                float4 a = dp[lane], b4 = dp[lane + 32];
                float4 c = lp[lane], d4 = lp[lane + 32];
                float sd = a.x+a.y+a.z+a.w + b4.x+b4.y+b4.z+b4.w;
                float sl = c.x+c.y+c.z+c.w + d4.x+d4.y+d4.z+d4.w;
                #pragma unroll
                for (int off = 16; off; off >>= 1) {
                    sd += __shfl_xor_sync(0xffffffffu, sd, off);
                    sl += __shfl_xor_sync(0xffffffffu, sl, off);
                }
                dtv = sd; pl = sl;
            }

            float o0, o1, o2, o3, o4;
            #pragma unroll
            for (int r = 0; r < 5; r++) {
                unsigned myb = __float_as_uint(v0);
                unsigned mxb = __reduce_max_sync(0xffffffffu, myb);
                unsigned msk = __ballot_sync(0xffffffffu, myb == mxb);
                if (lane == __ffs(msk) - 1) { v0 = v1; v1 = v2; v2 = v3; v3 = v4; v4 = 0.f; }
                float mx = __uint_as_float(mxb);
                if (r == 0) o0 = mx; else if (r == 1) o1 = mx;
                else if (r == 2) o2 = mx; else if (r == 3) o3 = mx; else o4 = mx;
            }

            if (lane == 0) {
                float ent  = -slp * LN2F;
                float mass = o0 + o1 + o2 + o3 + o4;
                float pn   = fmaxf(sqrtf(sq), FEPS);
                s_feat[0*EE + wid] = ent;
                s_feat[1*EE + wid] = mass;
                s_feat[2*EE + wid] = 1.f - mass;
                s_feat[3*EE + wid] = o0;
                s_feat[4*EE + wid] = o0 - o1;
                s_feat[5*EE + wid] = dtv / (pn * mn);
                s_feat[6*EE + wid] = (slp - pl) * LN2F;
                s_sq[wid] = sq;
            }
        }
        __syncthreads();

        if (tid == 0) {
            float totsq = 0.f;
            #pragma unroll
            for (int e = 0; e < EE; e++) totsq += s_sq[e];
            float mcv = (totsq - 8.f * s_ge2) * (1.f / 7000.f);
            float mu = 0.f;
            #pragma unroll
            for (int e = 0; e < EE; e++) mu += s_feat[3*EE + e];
            mu *= 0.125f;
            float var = 0.f;
            #pragma unroll
            for (int e = 0; e < EE; e++) {
                float d = s_feat[3*EE + e] - mu;
                var += d * d;
            }
            s_feat[56] = -s_gent * LN2F;
            s_feat[57] = mcv;
            s_feat[58] = sqrtf(var * (1.f/7.f));
        }
        __syncthreads();

        if (tid < DD) {
            float v = s_feat[tid];
            v = fminf(fmaxf(v, -100.f), 100.f);
            feats[(size_t)b * DD + tid] = v;
        }
        __syncthreads();
    }
}

// ---------------------------------------------------------------------------
// Kernel B: MLP, 4x4 register tiles, 32 rows per chunk, 512 threads.
// W1/W2 via LDG.128 (L1/L2 resident). smem ~66KB -> 2 blocks/SM.
// ---------------------------------------------------------------------------
#define RPC 32

__global__ void __launch_bounds__(512, 2) mlp_kernel(
    const float* __restrict__ feats,
    const float* __restrict__ W1, const float* __restrict__ b1,
    const float* __restrict__ g1, const float* __restrict__ be1,
    const float* __restrict__ W2, const float* __restrict__ b2,
    const float* __restrict__ g2, const float* __restrict__ be2,
    const float* __restrict__ W3, const float* __restrict__ b3,
    float* __restrict__ wout, float* __restrict__ lout)
{
    extern __shared__ float sm[];
    float* sf   = sm;                  // 32*60 = 1920
    float* sh1  = sf   + RPC*60;       // 32*256 = 8192
    float* sh2  = sh1  + RPC*HH1;      // 32*128 = 4096
    float* sW3  = sh2  + RPC*HH2;      // 128*8 = 1024
    float* sb1  = sW3  + HH2*EE;       // 256
    float* sg1  = sb1  + HH1;          // 256
    float* sbe1 = sg1  + HH1;          // 256
    float* sb2  = sbe1 + HH1;          // 128
    float* sg2  = sb2  + HH2;          // 128
    float* sbe2 = sg2  + HH2;          // 128
    float* sb3  = sbe2 + HH2;          // 8
    float* sred = sb3  + EE;           // 16 warps * 8 = 128

    const int tid  = threadIdx.x;
    const int lane = tid & 31;
    const int wid  = tid >> 5;

    for (int i = tid; i < HH2*EE; i += 512) sW3[i] = W3[i];
    for (int i = tid; i < HH1;    i += 512) { sb1[i] = b1[i]; sg1[i] = g1[i]; sbe1[i] = be1[i]; }
    for (int i = tid; i < HH2;    i += 512) { sb2[i] = b2[i]; sg2[i] = g2[i]; sbe2[i] = be2[i]; }
    if (tid < EE) sb3[tid] = b3[tid];
    __syncthreads();

    const int nchunks = BB / RPC;   // 512
    for (int chunk = blockIdx.x; chunk < nchunks; chunk += gridDim.x) {
        const int row0 = chunk * RPC;

        // ---- stage feats (stride-60 rows) ----
        for (int t = tid; t < RPC*DD; t += 512) {
            int r = t / DD;
            int i = t - r*DD;
            sf[r*60 + i] = feats[(size_t)row0 * DD + t];
        }
        __syncthreads();

        // ---- layer 1: 59 -> 256. 4 cols x 4 rows per thread ----
        {
            const int q   = tid & 63;          // col quad: cols 4q..4q+3
            const int rg  = tid >> 6;          // 8 rowgroups x 4 rows
            float acc[4][4];
            #pragma unroll
            for (int r = 0; r < 4; r++)
                #pragma unroll
                for (int c = 0; c < 4; c++) acc[r][c] = 0.f;

            const float4* w1q = reinterpret_cast<const float4*>(W1);
            #pragma unroll 4
            for (int i = 0; i < DD; i++) {
                float4 w = __ldg(&w1q[i*64 + q]);
                #pragma unroll
                for (int r = 0; r < 4; r++) {
                    float a = sf[(rg*4 + r)*60 + i];
                    acc[r][0] += a*w.x; acc[r][1] += a*w.y;
                    acc[r][2] += a*w.z; acc[r][3] += a*w.w;
                }
            }
            float4 bb = *reinterpret_cast<const float4*>(&sb1[4*q]);
            #pragma unroll
            for (int r = 0; r < 4; r++) {
                acc[r][0] += bb.x; acc[r][1] += bb.y;
                acc[r][2] += bb.z; acc[r][3] += bb.w;
            }

            // LN over 256 cols: per row, reduce 64 threads = 2 warps
            float s[4], qs[4];
            #pragma unroll
            for (int r = 0; r < 4; r++) {
                s[r]  = acc[r][0] + acc[r][1] + acc[r][2] + acc[r][3];
                qs[r] = acc[r][0]*acc[r][0] + acc[r][1]*acc[r][1]
                      + acc[r][2]*acc[r][2] + acc[r][3]*acc[r][3];
            }
            #pragma unroll
            for (int off = 16; off; off >>= 1) {
                #pragma unroll
                for (int r = 0; r < 4; r++) {
                    s[r]  += __shfl_xor_sync(0xffffffffu, s[r],  off);
                    qs[r] += __shfl_xor_sync(0xffffffffu, qs[r], off);
                }
            }
            if (lane == 0) {
                #pragma unroll
                for (int r = 0; r < 4; r++) {
                    sred[wid*8 + r]     = s[r];
                    sred[wid*8 + 4 + r] = qs[r];
                }
            }
            __syncthreads();

            float4 gg = *reinterpret_cast<const float4*>(&sg1[4*q]);
            float4 be = *reinterpret_cast<const float4*>(&sbe1[4*q]);
            #pragma unroll
            for (int r = 0; r < 4; r++) {
                float st = sred[(2*rg)*8 + r]     + sred[(2*rg+1)*8 + r];
                float qt = sred[(2*rg)*8 + 4 + r] + sred[(2*rg+1)*8 + 4 + r];
                float mu = st * (1.f/256.f);
                float rs = rsqrtf(qt * (1.f/256.f) - mu*mu + LNEPS);
                float4 hv;
                hv.x = fmaxf((acc[r][0]-mu)*rs*gg.x + be.x, 0.f);
                hv.y = fmaxf((acc[r][1]-mu)*rs*gg.y + be.y, 0.f);
                hv.z = fmaxf((acc[r][2]-mu)*rs*gg.z + be.z, 0.f);
                hv.w = fmaxf((acc[r][3]-mu)*rs*gg.w + be.w, 0.f);
                *reinterpret_cast<float4*>(&sh1[(rg*4 + r)*HH1 + 4*q]) = hv;
            }
        }
        __syncthreads();

        // ---- layer 2: 256 -> 128. 256 threads, 4 cols x 4 rows per thread ----
        if (tid < 256) {
            const int cq = tid & 31;           // cols 4cq..4cq+3
            const int rg = tid >> 5;           // 8 rowgroups x 4 rows (= wid, whole warp same rows)
            float acc[4][4];
            #pragma unroll
            for (int r = 0; r < 4; r++)
                #pragma unroll
                for (int c = 0; c < 4; c++) acc[r][c] = 0.f;

            const float4* w2q = reinterpret_cast<const float4*>(W2);
            #pragma unroll 4
            for (int i = 0; i < HH1; i++) {
                float4 w = __ldg(&w2q[i*32 + cq]);
                #pragma unroll
                for (int r = 0; r < 4; r++) {
                    float a = sh1[(rg*4 + r)*HH1 + i];
                    acc[r][0] += a*w.x; acc[r][1] += a*w.y;
                    acc[r][2] += a*w.z; acc[r][3] += a*w.w;
                }
            }
            float4 bb = *reinterpret_cast<const float4*>(&sb2[4*cq]);
            #pragma unroll
            for (int r = 0; r < 4; r++) {
                acc[r][0] += bb.x; acc[r][1] += bb.y;
                acc[r][2] += bb.z; acc[r][3] += bb.w;
            }

            // LN over 128 cols: whole warp owns these 4 rows -> pure butterfly
            float s[4], qs[4];
            #pragma unroll
            for (int r = 0; r < 4; r++) {
                s[r]  = acc[r][0] + acc[r][1] + acc[r][2] + acc[r][3];
                qs[r] = acc[r][0]*acc[r][0] + acc[r][1]*acc[r][1]
                      + acc[r][2]*acc[r][2] + acc[r][3]*acc[r][3];
            }
            #pragma unroll
            for (int off = 16; off; off >>= 1) {
                #pragma unroll
                for (int r = 0; r < 4; r++) {
                    s[r]  += __shfl_xor_sync(0xffffffffu, s[r],  off);
                    qs[r] += __shfl_xor_sync(0xffffffffu, qs[r], off);
                }
            }
            float4 gg = *reinterpret_cast<const float4*>(&sg2[4*cq]);
            float4 be = *reinterpret_cast<const float4*>(&sbe2[4*cq]);
            #pragma unroll
            for (int r = 0; r < 4; r++) {
                float mu = s[r] * (1.f/128.f);
                float rs = rsqrtf(qs[r] * (1.f/128.f) - mu*mu + LNEPS);
                float4 hv;
                hv.x = fmaxf((acc[r][0]-mu)*rs*gg.x + be.x, 0.f);
                hv.y = fmaxf((acc[r][1]-mu)*rs*gg.y + be.y, 0.f);
                hv.z = fmaxf((acc[r][2]-mu)*rs*gg.z + be.z, 0.f);
                hv.w = fmaxf((acc[r][3]-mu)*rs*gg.w + be.w, 0.f);
                *reinterpret_cast<float4*>(&sh2[(rg*4 + r)*HH2 + 4*cq]) = hv;
            }
        }
        __syncthreads();

        // ---- layer 3 + softmax: 256 threads = 32 rows x 8 outputs ----
        if (tid < RPC*EE) {
            const int r = tid >> 3;
            const int o = tid & 7;
            float a = sb3[o];
            #pragma unroll 8
            for (int i = 0; i < HH2; i++) a += sh2[r*HH2 + i] * sW3[i*EE + o];

            float mx = a;
            #pragma unroll
            for (int off = 4; off; off >>= 1)
                mx = fmaxf(mx, __shfl_xor_sync(0xffffffffu, mx, off));
            float ex = __expf(a - mx);
            float sme = ex;
            #pragma unroll
            for (int off = 4; off; off >>= 1)
                sme += __shfl_xor_sync(0xffffffffu, sme, off);
            const int row = row0 + r;
            lout[(size_t)row*EE + o] = a;
            wout[(size_t)row*EE + o] = ex / sme;
        }
        __syncthreads();
    }
}

// ---------------------------------------------------------------------------
extern "C" void kernel_launch(void* const* d_in, const int* in_sizes, int n_in,
                              void* d_out, int out_size)
{
    (void)in_sizes; (void)n_in; (void)out_size;
    const float* P   = (const float*)d_in[0];
    const float* W1  = (const float*)d_in[1];
    const float* b1  = (const float*)d_in[2];
    const float* g1  = (const float*)d_in[3];
    const float* be1 = (const float*)d_in[4];
    const float* W2  = (const float*)d_in[5];
    const float* b2  = (const float*)d_in[6];
    const float* g2  = (const float*)d_in[7];
    const float* be2 = (const float*)d_in[8];
    const float* W3  = (const float*)d_in[9];
    const float* b3  = (const float*)d_in[10];

    float* out   = (float*)d_out;
    float* wout  = out;                    // weights: B*8
    float* lout  = out + (size_t)BB*EE;    // logits:  B*8
    float* feats = out + (size_t)2*BB*EE;  // feats:   B*59

    const size_t smemA = (size_t)(EE*CC + 2*8*256) * sizeof(float);  // 48384 B
    cudaFuncSetAttribute(feat_kernel, cudaFuncAttributeMaxDynamicSharedMemorySize, (int)smemA);
    feat_kernel<<<592, 256, smemA>>>(P, feats);

    const size_t smemB = (size_t)(RPC*60 + RPC*HH1 + RPC*HH2 + HH2*EE
                                  + 3*HH1 + 3*HH2 + EE + 128) * sizeof(float);  // ~66KB
    cudaFuncSetAttribute(mlp_kernel, cudaFuncAttributeMaxDynamicSharedMemorySize, (int)smemB);
    mlp_kernel<<<296, 512, smemB>>>(feats, W1, b1, g1, be1, W2, b2, g2, be2, W3, b3,
                                    wout, lout);
}